// round 14
// baseline (speedup 1.0000x reference)
#include <cuda_runtime.h>
#include <cuda_bf16.h>
#include <math.h>
#include <stdint.h>

// Problem constants
#define Bv 8
#define Tv 1024
#define Cv 16
#define Lv 1040      // C + T
#define Dv 512
#define Hv 8
#define DHv 64
#define NLv 2
#define DFFv 2048
#define VSv 8000     // V*S
#define Sv 8

// ---------------- scratch (static device globals; allocation-free) ----------
__device__ float g_X  [Bv * Lv * Dv];
__device__ float g_MEM[Bv * Lv * Dv];
__device__ float g_Qt [Bv * Hv * Lv * DHv];
__device__ float g_Kt [Bv * Hv * Lv * DHv];
__device__ float g_Vt [Bv * Hv * Lv * DHv];
__device__ float g_att[(long)Bv * Hv * Lv * Lv];
__device__ float g_ctx[Bv * Lv * Dv];
__device__ float g_Y  [Bv * Lv * Dv];
__device__ float g_Hff[Bv * Lv * DFFv];

// ---------------- embed ------------------------------------------------------
__global__ __launch_bounds__(256) void embed_kernel(
    const int* __restrict__ token, const int* __restrict__ state,
    const float* __restrict__ prefix, const float* __restrict__ emb,
    const float* __restrict__ b_in, const float* __restrict__ pos,
    float* __restrict__ X, float* __restrict__ MEM)
{
    long i = (long)blockIdx.x * 256 + threadIdx.x;
    if (i >= (long)Bv * Lv * Dv) return;
    int d = (int)(i & (Dv - 1));
    long r = i >> 9;
    int l = (int)(r % Lv);
    int b = (int)(r / Lv);
    float v;
    if (l < Cv) {
        v = prefix[((long)b * Cv + l) * Dv + d];
    } else {
        int t = l - Cv;
        int row = token[b * Tv + t] * Sv + state[b];
        v = emb[(long)row * Dv + d] + b_in[d];
    }
    v += pos[(long)l * Dv + d];
    X[i] = v;
    MEM[i] = v;
}

// ---------------- tf32 tensor-core GEMM, cp.async double-buffered ------------
// C = alpha * A * op(B) + bias ; A:[M,K] lda ; B: TRANSB? [N,K]:[K,N] ldb
// flags: bit1 = relu ; bit2 = QKV head epilogue (C=K/Q head buf, C2=V half)
//        bit3 = ctx epilogue (z=b*H+h, write [b, l, h*64+d])
// Tile: BM=BN=128, BK=16, 256 thr = 8 warps (4Mx2N), warp tile 32x64.

__device__ __forceinline__ void cp16(float* dst, const float* src, int szbytes) {
    uint32_t d = (uint32_t)__cvta_generic_to_shared(dst);
    asm volatile("cp.async.cg.shared.global [%0], [%1], 16, %2;\n"
                 :: "r"(d), "l"(src), "r"(szbytes));
}
__device__ __forceinline__ void cp_commit() {
    asm volatile("cp.async.commit_group;\n");
}
__device__ __forceinline__ uint32_t ldcvt(const float* p) {
    uint32_t r;
    asm("cvt.rna.tf32.f32 %0, %1;" : "=r"(r) : "f"(*p));
    return r;
}
__device__ __forceinline__ void mma_tf32(float* d, const uint32_t* a,
                                         uint32_t b0, uint32_t b1) {
    asm volatile(
        "mma.sync.aligned.m16n8k8.row.col.f32.tf32.tf32.f32 "
        "{%0,%1,%2,%3}, {%4,%5,%6,%7}, {%8,%9}, {%0,%1,%2,%3};\n"
        : "+f"(d[0]), "+f"(d[1]), "+f"(d[2]), "+f"(d[3])
        : "r"(a[0]), "r"(a[1]), "r"(a[2]), "r"(a[3]), "r"(b0), "r"(b1));
}

// A tile: [128 rows][16 k], row stride 20 floats (bank map g*20+t -> distinct)
// B NT  : [128 rows][16 k], row stride 20
// B NN  : [16 k][128 n],    row stride 136 (bank map t*8+g -> distinct)
template<bool TRANSB>
__device__ __forceinline__ void load_tile(
    float* sa, float* sb, const float* A, const float* Bm,
    int m0, int n0, int koff, int M, int N, int lda, int ldb, int tid)
{
#pragma unroll
    for (int it = 0; it < 2; it++) {
        int idx = tid + it * 256;
        int row = idx >> 2, ch = (idx & 3) << 2;
        const float* src = A + (long)(m0 + row) * lda + koff + ch;
        int sz = 16;
        if (m0 + row >= M) { sz = 0; src = A; }
        cp16(sa + row * 20 + ch, src, sz);
    }
    if (TRANSB) {
#pragma unroll
        for (int it = 0; it < 2; it++) {
            int idx = tid + it * 256;
            int row = idx >> 2, ch = (idx & 3) << 2;
            const float* src = Bm + (long)(n0 + row) * ldb + koff + ch;
            int sz = 16;
            if (n0 + row >= N) { sz = 0; src = Bm; }
            cp16(sb + row * 20 + ch, src, sz);
        }
    } else {
#pragma unroll
        for (int it = 0; it < 2; it++) {
            int idx = tid + it * 256;
            int k = idx >> 5, ch = (idx & 31) << 2;
            const float* src = Bm + (long)(koff + k) * ldb + n0 + ch;
            int rem = N - (n0 + ch);
            int sz = rem >= 4 ? 16 : (rem > 0 ? rem * 4 : 0);
            if (sz == 0) src = Bm;
            cp16(sb + k * 136 + ch, src, sz);
        }
    }
    cp_commit();
}

template<bool TRANSB>
__global__ __launch_bounds__(256) void gemm_tc_kernel(
    const float* __restrict__ A, const float* __restrict__ Bm,
    const float* __restrict__ bias, float* __restrict__ C, float* __restrict__ C2,
    int M, int N, int K, int lda, int ldb, int ldc,
    long strA, long strB, long strC, float alpha, int flags)
{
    __shared__ __align__(16) float sA[2][128 * 20];
    __shared__ __align__(16) float sB[2][2560];   // NT: 128*20 ; NN: 16*136

    int z = blockIdx.z;
    A  += (long)z * strA;
    Bm += (long)z * strB;
    C  += (long)z * strC;
    int m0 = blockIdx.y * 128, n0 = blockIdx.x * 128;
    int tid = threadIdx.x;
    int warp = tid >> 5, lane = tid & 31;
    int wm = warp >> 1, wn = warp & 1;
    int g = lane >> 2, t = lane & 3;

    float acc[2][8][4];
#pragma unroll
    for (int mt = 0; mt < 2; mt++)
#pragma unroll
        for (int nt = 0; nt < 8; nt++)
#pragma unroll
            for (int q = 0; q < 4; q++) acc[mt][nt][q] = 0.f;

    const int nk = K >> 4;   // all K multiples of 16

    load_tile<TRANSB>(sA[0], sB[0], A, Bm, m0, n0, 0, M, N, lda, ldb, tid);

    for (int kt = 0; kt < nk; kt++) {
        int cur = kt & 1;
        if (kt + 1 < nk) {
            load_tile<TRANSB>(sA[1 - cur], sB[1 - cur], A, Bm, m0, n0,
                              (kt + 1) << 4, M, N, lda, ldb, tid);
            asm volatile("cp.async.wait_group 1;\n");
        } else {
            asm volatile("cp.async.wait_group 0;\n");
        }
        __syncthreads();

        const float* sa = sA[cur];
        const float* sb = sB[cur];
#pragma unroll
        for (int ks = 0; ks < 2; ks++) {
            int k0 = ks * 8;
            uint32_t aF[2][4];
#pragma unroll
            for (int mt = 0; mt < 2; mt++) {
                int rb = wm * 32 + mt * 16;
                aF[mt][0] = ldcvt(&sa[(rb + g) * 20 + k0 + t]);
                aF[mt][1] = ldcvt(&sa[(rb + g + 8) * 20 + k0 + t]);
                aF[mt][2] = ldcvt(&sa[(rb + g) * 20 + k0 + t + 4]);
                aF[mt][3] = ldcvt(&sa[(rb + g + 8) * 20 + k0 + t + 4]);
            }
#pragma unroll
            for (int nt = 0; nt < 8; nt++) {
                int cb = wn * 64 + nt * 8;
                uint32_t b0, b1;
                if (TRANSB) {
                    b0 = ldcvt(&sb[(cb + g) * 20 + k0 + t]);
                    b1 = ldcvt(&sb[(cb + g) * 20 + k0 + t + 4]);
                } else {
                    b0 = ldcvt(&sb[(k0 + t) * 136 + cb + g]);
                    b1 = ldcvt(&sb[(k0 + t + 4) * 136 + cb + g]);
                }
                mma_tf32(acc[0][nt], aF[0], b0, b1);
                mma_tf32(acc[1][nt], aF[1], b0, b1);
            }
        }
        __syncthreads();
    }

    // ---------------- epilogue ----------------
    const bool relu = (flags & 2);
#pragma unroll
    for (int mt = 0; mt < 2; mt++) {
        int rowA = m0 + wm * 32 + mt * 16 + g;
#pragma unroll
        for (int half = 0; half < 2; half++) {
            int row = rowA + half * 8;
            if (row >= M) continue;
#pragma unroll
            for (int nt = 0; nt < 8; nt++) {
                int col = n0 + wn * 64 + nt * 8 + t * 2;
                if (col >= N) continue;   // N even, col even
                float v0 = acc[mt][nt][half * 2 + 0] * alpha;
                float v1 = acc[mt][nt][half * 2 + 1] * alpha;
                if (bias) { v0 += bias[col]; v1 += bias[col + 1]; }
                if (relu) { v0 = fmaxf(v0, 0.f); v1 = fmaxf(v1, 0.f); }
                float* dst;
                if (flags & 4) {          // QKV head epilogue
                    float* base = C; int c = col;
                    if (c >= Dv) { base = C2; c -= Dv; }
                    int b = row / Lv, l = row - b * Lv;
                    dst = base + (((long)(b * Hv + (c >> 6)) * Lv + l) << 6) + (c & 63);
                } else if (flags & 8) {   // ctx epilogue: z=b*H+h, row=l, col=d
                    int b = z >> 3, h = z & 7;
                    dst = C + ((long)(b * Lv + row) * Dv) + (h << 6) + col;
                } else {
                    dst = C + (long)row * ldc + col;
                }
                *(float2*)dst = make_float2(v0, v1);
            }
        }
    }
}

// ---------------- softmax ------------------------------------------------------
__global__ __launch_bounds__(256) void softmax_kernel(float* __restrict__ att)
{
    long row = blockIdx.x;
    float* p = att + row * (long)Lv;
    int tid = threadIdx.x;
    float vals[5];
    int cnt = 0;
    float mx = -1e30f;
    for (int c = tid; c < Lv; c += 256) { vals[cnt] = p[c]; mx = fmaxf(mx, vals[cnt]); cnt++; }
    __shared__ float red[256];
    red[tid] = mx; __syncthreads();
#pragma unroll
    for (int s = 128; s > 0; s >>= 1) { if (tid < s) red[tid] = fmaxf(red[tid], red[tid + s]); __syncthreads(); }
    mx = red[0]; __syncthreads();
    float sum = 0.f;
    for (int i = 0; i < cnt; i++) { vals[i] = expf(vals[i] - mx); sum += vals[i]; }
    red[tid] = sum; __syncthreads();
#pragma unroll
    for (int s = 128; s > 0; s >>= 1) { if (tid < s) red[tid] += red[tid + s]; __syncthreads(); }
    float inv = 1.f / red[0];
    cnt = 0;
    for (int c = tid; c < Lv; c += 256) { p[c] = vals[cnt] * inv; cnt++; }
}

// ---------------- residual + LayerNorm ----------------------------------------
__global__ __launch_bounds__(256) void ln_kernel(
    float* __restrict__ X, const float* __restrict__ Y,
    const float* __restrict__ g, const float* __restrict__ b)
{
    long row = blockIdx.x;
    float* x = X + row * (long)Dv;
    const float* y = Y + row * (long)Dv;
    int tid = threadIdx.x;
    float v0 = x[tid] + y[tid];
    float v1 = x[tid + 256] + y[tid + 256];
    __shared__ float red[256];
    red[tid] = v0 + v1; __syncthreads();
#pragma unroll
    for (int s = 128; s > 0; s >>= 1) { if (tid < s) red[tid] += red[tid + s]; __syncthreads(); }
    float mu = red[0] * (1.f / Dv); __syncthreads();
    float d0 = v0 - mu, d1 = v1 - mu;
    red[tid] = d0 * d0 + d1 * d1; __syncthreads();
#pragma unroll
    for (int s = 128; s > 0; s >>= 1) { if (tid < s) red[tid] += red[tid + s]; __syncthreads(); }
    float rstd = rsqrtf(red[0] * (1.f / Dv) + 1e-5f);
    x[tid]       = d0 * rstd * g[tid]       + b[tid];
    x[tid + 256] = d1 * rstd * g[tid + 256] + b[tid + 256];
}

// ---------------- host orchestration -----------------------------------------
static inline dim3 ggrid(int M, int N, int batch) {
    return dim3((N + 127) / 128, (M + 127) / 128, batch);
}

#define GEMM_NT(Aa,Bb,bi,Cc,C2,M,N,K,lda,ldb,ldc,sA,sB,sC,al,fl) \
    gemm_tc_kernel<true><<<ggrid(M,N, (sA||sB||sC)?((sC== (long)Lv*Lv)?Bv*Hv:Bv):1 ), 256>>>(0,0,0,0,0,0,0,0,0,0,0,0,0,0,0.f,0)
// (macro unused; explicit launches below)

extern "C" void kernel_launch(void* const* d_in, const int* in_sizes, int n_in,
                              void* d_out, int out_size)
{
    const int*   token  = (const int*)  d_in[0];
    const int*   state  = (const int*)  d_in[1];
    const float* prefix = (const float*)d_in[2];
    const float* emb    = (const float*)d_in[3];
    const float* b_in   = (const float*)d_in[4];
    const float* pos    = (const float*)d_in[5];
    const float* W_out  = (const float*)d_in[6];
    const float* b_out  = (const float*)d_in[7];
    const float* qkv_w  = (const float*)d_in[8];
    const float* qkv_b  = (const float*)d_in[9];
    const float* out_w  = (const float*)d_in[10];
    const float* out_b  = (const float*)d_in[11];
    const float* lin1_w = (const float*)d_in[12];
    const float* lin1_b = (const float*)d_in[13];
    const float* lin2_w = (const float*)d_in[14];
    const float* lin2_b = (const float*)d_in[15];
    const float* ln_g   = (const float*)d_in[16];
    const float* ln_b   = (const float*)d_in[17];
    float* out = (float*)d_out;

    float *X, *MEM, *Qt, *Kt, *Vt, *att, *ctx, *Y, *Hff;
    cudaGetSymbolAddress((void**)&X,   g_X);
    cudaGetSymbolAddress((void**)&MEM, g_MEM);
    cudaGetSymbolAddress((void**)&Qt,  g_Qt);
    cudaGetSymbolAddress((void**)&Kt,  g_Kt);
    cudaGetSymbolAddress((void**)&Vt,  g_Vt);
    cudaGetSymbolAddress((void**)&att, g_att);
    cudaGetSymbolAddress((void**)&ctx, g_ctx);
    cudaGetSymbolAddress((void**)&Y,   g_Y);
    cudaGetSymbolAddress((void**)&Hff, g_Hff);

    const int BL = Bv * Lv;
    const long nEmb = (long)Bv * Lv * Dv;

    embed_kernel<<<(int)((nEmb + 255) / 256), 256>>>(token, state, prefix, emb, b_in, pos, X, MEM);

    const float scale = 1.f / 8.f;

    for (int i = 0; i < NLv; i++) {
        for (int j = 0; j < 2; j++) {
            const float* kvsrc = (j == 0) ? X : MEM;
            const float* w  = qkv_w + (long)(i * 2 + j) * 3 * Dv * Dv;
            const float* bb = qkv_b + (long)(i * 2 + j) * 3 * Dv;

            // Qt[b,h,l,d] = X @ Wq^T + bq  (head epilogue)
            gemm_tc_kernel<true><<<ggrid(BL, Dv, 1), 256>>>(X, w, bb, Qt, Qt,
                BL, Dv, Dv, Dv, Dv, Dv, 0, 0, 0, 1.f, 4);
            // Kt|Vt = kvsrc @ [Wk;Wv]^T + b  (head epilogue, split at 512)
            gemm_tc_kernel<true><<<ggrid(BL, 2 * Dv, 1), 256>>>(kvsrc, w + (long)Dv * Dv, bb + Dv, Kt, Vt,
                BL, 2 * Dv, Dv, Dv, Dv, 2 * Dv, 0, 0, 0, 1.f, 4);

            // att = scale * Qt @ Kt^T per (b,h)
            gemm_tc_kernel<true><<<ggrid(Lv, Lv, Bv * Hv), 256>>>(Qt, Kt, nullptr, att, att,
                Lv, Lv, DHv, DHv, DHv, Lv,
                (long)Lv * DHv, (long)Lv * DHv, (long)Lv * Lv, scale, 0);

            softmax_kernel<<<Bv * Hv * Lv, 256>>>(att);

            // ctx[b,l,h*64+d] = att @ Vt per (b,h)  (ctx epilogue)
            gemm_tc_kernel<false><<<ggrid(Lv, DHv, Bv * Hv), 256>>>(att, Vt, nullptr, ctx, ctx,
                Lv, DHv, Lv, Lv, DHv, DHv,
                (long)Lv * Lv, (long)Lv * DHv, 0, 1.f, 8);

            // Y = ctx @ Wo^T + bo
            gemm_tc_kernel<true><<<ggrid(BL, Dv, 1), 256>>>(ctx,
                out_w + (long)(i * 2 + j) * Dv * Dv, out_b + (long)(i * 2 + j) * Dv, Y, Y,
                BL, Dv, Dv, Dv, Dv, Dv, 0, 0, 0, 1.f, 0);

            ln_kernel<<<BL, 256>>>(X, Y,
                ln_g + (long)(i * 3 + j) * Dv, ln_b + (long)(i * 3 + j) * Dv);
        }
        gemm_tc_kernel<true><<<ggrid(BL, DFFv, 1), 256>>>(X,
            lin1_w + (long)i * DFFv * Dv, lin1_b + (long)i * DFFv, Hff, Hff,
            BL, DFFv, Dv, Dv, Dv, DFFv, 0, 0, 0, 1.f, 2);
        gemm_tc_kernel<true><<<ggrid(BL, Dv, 1), 256>>>(Hff,
            lin2_w + (long)i * Dv * DFFv, lin2_b + (long)i * Dv, Y, Y,
            BL, Dv, DFFv, DFFv, DFFv, Dv, 0, 0, 0, 1.f, 0);
        ln_kernel<<<BL, 256>>>(X, Y,
            ln_g + (long)(i * 3 + 2) * Dv, ln_b + (long)(i * 3 + 2) * Dv);
    }

    // logits: per batch b, [Tv,VSv] = X[b,C:] @ W_out^T + b_out
    gemm_tc_kernel<true><<<ggrid(Tv, VSv, Bv), 256>>>(X + (long)Cv * Dv, W_out, b_out, out, out,
        Tv, VSv, Dv, Dv, Dv, VSv,
        (long)Lv * Dv, 0, (long)Tv * VSv, 1.f, 0);
}

// round 15
// speedup vs baseline: 1.0026x; 1.0026x over previous
#include <cuda_runtime.h>
#include <cuda_bf16.h>
#include <math.h>
#include <stdint.h>

// Problem constants
#define Bv 8
#define Tv 1024
#define Cv 16
#define Lv 1040      // C + T
#define Dv 512
#define Hv 8
#define DHv 64
#define NLv 2
#define DFFv 2048
#define VSv 8000     // V*S
#define Sv 8

// ---------------- scratch (static device globals; allocation-free) ----------
__device__ float g_X  [Bv * Lv * Dv];
__device__ float g_MEM[Bv * Lv * Dv];
__device__ float g_Qt [Bv * Hv * Lv * DHv];
__device__ float g_Kt [Bv * Hv * Lv * DHv];
__device__ float g_Vt [Bv * Hv * Lv * DHv];
__device__ float g_att[(long)Bv * Hv * Lv * Lv];
__device__ float g_ctx[Bv * Lv * Dv];
__device__ float g_Y  [Bv * Lv * Dv];
__device__ float g_Hff[Bv * Lv * DFFv];

// ---------------- embed ------------------------------------------------------
__global__ __launch_bounds__(256) void embed_kernel(
    const int* __restrict__ token, const int* __restrict__ state,
    const float* __restrict__ prefix, const float* __restrict__ emb,
    const float* __restrict__ b_in, const float* __restrict__ pos,
    float* __restrict__ X, float* __restrict__ MEM)
{
    long i = (long)blockIdx.x * 256 + threadIdx.x;
    if (i >= (long)Bv * Lv * Dv) return;
    int d = (int)(i & (Dv - 1));
    long r = i >> 9;
    int l = (int)(r % Lv);
    int b = (int)(r / Lv);
    float v;
    if (l < Cv) {
        v = prefix[((long)b * Cv + l) * Dv + d];
    } else {
        int t = l - Cv;
        int row = token[b * Tv + t] * Sv + state[b];
        v = emb[(long)row * Dv + d] + b_in[d];
    }
    v += pos[(long)l * Dv + d];
    X[i] = v;
    MEM[i] = v;
}

// ---------------- tf32 tensor-core GEMM, cp.async double-buffered ------------
// C = alpha * A * op(B) + bias ; A:[M,K] lda ; B: TRANSB? [N,K]:[K,N] ldb
// flags: bit1 = relu ; bit2 = QKV head epilogue (C=K/Q head buf, C2=V half)
//        bit3 = ctx epilogue (z=b*H+h, write [b, l, h*64+d])
// Tile: BM=BN=128, BK=16, 256 thr = 8 warps (4Mx2N), warp tile 32x64.

__device__ __forceinline__ void cp16(float* dst, const float* src, int szbytes) {
    uint32_t d = (uint32_t)__cvta_generic_to_shared(dst);
    asm volatile("cp.async.cg.shared.global [%0], [%1], 16, %2;\n"
                 :: "r"(d), "l"(src), "r"(szbytes));
}
__device__ __forceinline__ void cp_commit() {
    asm volatile("cp.async.commit_group;\n");
}
__device__ __forceinline__ uint32_t ldcvt(const float* p) {
    uint32_t r;
    asm("cvt.rna.tf32.f32 %0, %1;" : "=r"(r) : "f"(*p));
    return r;
}
__device__ __forceinline__ void mma_tf32(float* d, const uint32_t* a,
                                         uint32_t b0, uint32_t b1) {
    asm volatile(
        "mma.sync.aligned.m16n8k8.row.col.f32.tf32.tf32.f32 "
        "{%0,%1,%2,%3}, {%4,%5,%6,%7}, {%8,%9}, {%0,%1,%2,%3};\n"
        : "+f"(d[0]), "+f"(d[1]), "+f"(d[2]), "+f"(d[3])
        : "r"(a[0]), "r"(a[1]), "r"(a[2]), "r"(a[3]), "r"(b0), "r"(b1));
}

// A tile: [128 rows][16 k], row stride 20 floats (bank map g*20+t -> distinct)
// B NT  : [128 rows][16 k], row stride 20
// B NN  : [16 k][128 n],    row stride 136 (bank map t*8+g -> distinct)
template<bool TRANSB>
__device__ __forceinline__ void load_tile(
    float* sa, float* sb, const float* A, const float* Bm,
    int m0, int n0, int koff, int M, int N, int lda, int ldb, int tid)
{
#pragma unroll
    for (int it = 0; it < 2; it++) {
        int idx = tid + it * 256;
        int row = idx >> 2, ch = (idx & 3) << 2;
        const float* src = A + (long)(m0 + row) * lda + koff + ch;
        int sz = 16;
        if (m0 + row >= M) { sz = 0; src = A; }
        cp16(sa + row * 20 + ch, src, sz);
    }
    if (TRANSB) {
#pragma unroll
        for (int it = 0; it < 2; it++) {
            int idx = tid + it * 256;
            int row = idx >> 2, ch = (idx & 3) << 2;
            const float* src = Bm + (long)(n0 + row) * ldb + koff + ch;
            int sz = 16;
            if (n0 + row >= N) { sz = 0; src = Bm; }
            cp16(sb + row * 20 + ch, src, sz);
        }
    } else {
#pragma unroll
        for (int it = 0; it < 2; it++) {
            int idx = tid + it * 256;
            int k = idx >> 5, ch = (idx & 31) << 2;
            const float* src = Bm + (long)(koff + k) * ldb + n0 + ch;
            int rem = N - (n0 + ch);
            int sz = rem >= 4 ? 16 : (rem > 0 ? rem * 4 : 0);
            if (sz == 0) src = Bm;
            cp16(sb + k * 136 + ch, src, sz);
        }
    }
    cp_commit();
}

template<bool TRANSB>
__global__ __launch_bounds__(256) void gemm_tc_kernel(
    const float* __restrict__ A, const float* __restrict__ Bm,
    const float* __restrict__ bias, float* __restrict__ C, float* __restrict__ C2,
    int M, int N, int K, int lda, int ldb, int ldc,
    long strA, long strB, long strC, float alpha, int flags)
{
    __shared__ __align__(16) float sA[2][128 * 20];
    __shared__ __align__(16) float sB[2][2560];   // NT: 128*20 ; NN: 16*136

    int z = blockIdx.z;
    A  += (long)z * strA;
    Bm += (long)z * strB;
    C  += (long)z * strC;
    int m0 = blockIdx.y * 128, n0 = blockIdx.x * 128;
    int tid = threadIdx.x;
    int warp = tid >> 5, lane = tid & 31;
    int wm = warp >> 1, wn = warp & 1;
    int g = lane >> 2, t = lane & 3;

    float acc[2][8][4];
#pragma unroll
    for (int mt = 0; mt < 2; mt++)
#pragma unroll
        for (int nt = 0; nt < 8; nt++)
#pragma unroll
            for (int q = 0; q < 4; q++) acc[mt][nt][q] = 0.f;

    const int nk = K >> 4;   // all K multiples of 16

    load_tile<TRANSB>(sA[0], sB[0], A, Bm, m0, n0, 0, M, N, lda, ldb, tid);

    for (int kt = 0; kt < nk; kt++) {
        int cur = kt & 1;
        if (kt + 1 < nk) {
            load_tile<TRANSB>(sA[1 - cur], sB[1 - cur], A, Bm, m0, n0,
                              (kt + 1) << 4, M, N, lda, ldb, tid);
            asm volatile("cp.async.wait_group 1;\n");
        } else {
            asm volatile("cp.async.wait_group 0;\n");
        }
        __syncthreads();

        const float* sa = sA[cur];
        const float* sb = sB[cur];
#pragma unroll
        for (int ks = 0; ks < 2; ks++) {
            int k0 = ks * 8;
            uint32_t aF[2][4];
#pragma unroll
            for (int mt = 0; mt < 2; mt++) {
                int rb = wm * 32 + mt * 16;
                aF[mt][0] = ldcvt(&sa[(rb + g) * 20 + k0 + t]);
                aF[mt][1] = ldcvt(&sa[(rb + g + 8) * 20 + k0 + t]);
                aF[mt][2] = ldcvt(&sa[(rb + g) * 20 + k0 + t + 4]);
                aF[mt][3] = ldcvt(&sa[(rb + g + 8) * 20 + k0 + t + 4]);
            }
#pragma unroll
            for (int nt = 0; nt < 8; nt++) {
                int cb = wn * 64 + nt * 8;
                uint32_t b0, b1;
                if (TRANSB) {
                    b0 = ldcvt(&sb[(cb + g) * 20 + k0 + t]);
                    b1 = ldcvt(&sb[(cb + g) * 20 + k0 + t + 4]);
                } else {
                    b0 = ldcvt(&sb[(k0 + t) * 136 + cb + g]);
                    b1 = ldcvt(&sb[(k0 + t + 4) * 136 + cb + g]);
                }
                mma_tf32(acc[0][nt], aF[0], b0, b1);
                mma_tf32(acc[1][nt], aF[1], b0, b1);
            }
        }
        __syncthreads();
    }

    // ---------------- epilogue ----------------
    const bool relu = (flags & 2);
#pragma unroll
    for (int mt = 0; mt < 2; mt++) {
        int rowA = m0 + wm * 32 + mt * 16 + g;
#pragma unroll
        for (int half = 0; half < 2; half++) {
            int row = rowA + half * 8;
            if (row >= M) continue;
#pragma unroll
            for (int nt = 0; nt < 8; nt++) {
                int col = n0 + wn * 64 + nt * 8 + t * 2;
                if (col >= N) continue;   // N even, col even
                float v0 = acc[mt][nt][half * 2 + 0] * alpha;
                float v1 = acc[mt][nt][half * 2 + 1] * alpha;
                if (bias) { v0 += bias[col]; v1 += bias[col + 1]; }
                if (relu) { v0 = fmaxf(v0, 0.f); v1 = fmaxf(v1, 0.f); }
                float* dst;
                if (flags & 4) {          // QKV head epilogue
                    float* base = C; int c = col;
                    if (c >= Dv) { base = C2; c -= Dv; }
                    int b = row / Lv, l = row - b * Lv;
                    dst = base + (((long)(b * Hv + (c >> 6)) * Lv + l) << 6) + (c & 63);
                } else if (flags & 8) {   // ctx epilogue: z=b*H+h, row=l, col=d
                    int b = z >> 3, h = z & 7;
                    dst = C + ((long)(b * Lv + row) * Dv) + (h << 6) + col;
                } else {
                    dst = C + (long)row * ldc + col;
                }
                *(float2*)dst = make_float2(v0, v1);
            }
        }
    }
}

// ---------------- softmax ------------------------------------------------------
__global__ __launch_bounds__(256) void softmax_kernel(float* __restrict__ att)
{
    long row = blockIdx.x;
    float* p = att + row * (long)Lv;
    int tid = threadIdx.x;
    float vals[5];
    int cnt = 0;
    float mx = -1e30f;
    for (int c = tid; c < Lv; c += 256) { vals[cnt] = p[c]; mx = fmaxf(mx, vals[cnt]); cnt++; }
    __shared__ float red[256];
    red[tid] = mx; __syncthreads();
#pragma unroll
    for (int s = 128; s > 0; s >>= 1) { if (tid < s) red[tid] = fmaxf(red[tid], red[tid + s]); __syncthreads(); }
    mx = red[0]; __syncthreads();
    float sum = 0.f;
    for (int i = 0; i < cnt; i++) { vals[i] = expf(vals[i] - mx); sum += vals[i]; }
    red[tid] = sum; __syncthreads();
#pragma unroll
    for (int s = 128; s > 0; s >>= 1) { if (tid < s) red[tid] += red[tid + s]; __syncthreads(); }
    float inv = 1.f / red[0];
    cnt = 0;
    for (int c = tid; c < Lv; c += 256) { p[c] = vals[cnt] * inv; cnt++; }
}

// ---------------- residual + LayerNorm ----------------------------------------
__global__ __launch_bounds__(256) void ln_kernel(
    float* __restrict__ X, const float* __restrict__ Y,
    const float* __restrict__ g, const float* __restrict__ b)
{
    long row = blockIdx.x;
    float* x = X + row * (long)Dv;
    const float* y = Y + row * (long)Dv;
    int tid = threadIdx.x;
    float v0 = x[tid] + y[tid];
    float v1 = x[tid + 256] + y[tid + 256];
    __shared__ float red[256];
    red[tid] = v0 + v1; __syncthreads();
#pragma unroll
    for (int s = 128; s > 0; s >>= 1) { if (tid < s) red[tid] += red[tid + s]; __syncthreads(); }
    float mu = red[0] * (1.f / Dv); __syncthreads();
    float d0 = v0 - mu, d1 = v1 - mu;
    red[tid] = d0 * d0 + d1 * d1; __syncthreads();
#pragma unroll
    for (int s = 128; s > 0; s >>= 1) { if (tid < s) red[tid] += red[tid + s]; __syncthreads(); }
    float rstd = rsqrtf(red[0] * (1.f / Dv) + 1e-5f);
    x[tid]       = d0 * rstd * g[tid]       + b[tid];
    x[tid + 256] = d1 * rstd * g[tid + 256] + b[tid + 256];
}

// ---------------- host orchestration -----------------------------------------
static inline dim3 ggrid(int M, int N, int batch) {
    return dim3((N + 127) / 128, (M + 127) / 128, batch);
}

#define GEMM_NT(Aa,Bb,bi,Cc,C2,M,N,K,lda,ldb,ldc,sA,sB,sC,al,fl) \
    gemm_tc_kernel<true><<<ggrid(M,N, (sA||sB||sC)?((sC== (long)Lv*Lv)?Bv*Hv:Bv):1 ), 256>>>(0,0,0,0,0,0,0,0,0,0,0,0,0,0,0.f,0)
// (macro unused; explicit launches below)

extern "C" void kernel_launch(void* const* d_in, const int* in_sizes, int n_in,
                              void* d_out, int out_size)
{
    const int*   token  = (const int*)  d_in[0];
    const int*   state  = (const int*)  d_in[1];
    const float* prefix = (const float*)d_in[2];
    const float* emb    = (const float*)d_in[3];
    const float* b_in   = (const float*)d_in[4];
    const float* pos    = (const float*)d_in[5];
    const float* W_out  = (const float*)d_in[6];
    const float* b_out  = (const float*)d_in[7];
    const float* qkv_w  = (const float*)d_in[8];
    const float* qkv_b  = (const float*)d_in[9];
    const float* out_w  = (const float*)d_in[10];
    const float* out_b  = (const float*)d_in[11];
    const float* lin1_w = (const float*)d_in[12];
    const float* lin1_b = (const float*)d_in[13];
    const float* lin2_w = (const float*)d_in[14];
    const float* lin2_b = (const float*)d_in[15];
    const float* ln_g   = (const float*)d_in[16];
    const float* ln_b   = (const float*)d_in[17];
    float* out = (float*)d_out;

    float *X, *MEM, *Qt, *Kt, *Vt, *att, *ctx, *Y, *Hff;
    cudaGetSymbolAddress((void**)&X,   g_X);
    cudaGetSymbolAddress((void**)&MEM, g_MEM);
    cudaGetSymbolAddress((void**)&Qt,  g_Qt);
    cudaGetSymbolAddress((void**)&Kt,  g_Kt);
    cudaGetSymbolAddress((void**)&Vt,  g_Vt);
    cudaGetSymbolAddress((void**)&att, g_att);
    cudaGetSymbolAddress((void**)&ctx, g_ctx);
    cudaGetSymbolAddress((void**)&Y,   g_Y);
    cudaGetSymbolAddress((void**)&Hff, g_Hff);

    const int BL = Bv * Lv;
    const long nEmb = (long)Bv * Lv * Dv;

    embed_kernel<<<(int)((nEmb + 255) / 256), 256>>>(token, state, prefix, emb, b_in, pos, X, MEM);

    const float scale = 1.f / 8.f;

    for (int i = 0; i < NLv; i++) {
        for (int j = 0; j < 2; j++) {
            const float* kvsrc = (j == 0) ? X : MEM;
            const float* w  = qkv_w + (long)(i * 2 + j) * 3 * Dv * Dv;
            const float* bb = qkv_b + (long)(i * 2 + j) * 3 * Dv;

            // Qt[b,h,l,d] = X @ Wq^T + bq  (head epilogue)
            gemm_tc_kernel<true><<<ggrid(BL, Dv, 1), 256>>>(X, w, bb, Qt, Qt,
                BL, Dv, Dv, Dv, Dv, Dv, 0, 0, 0, 1.f, 4);
            // Kt|Vt = kvsrc @ [Wk;Wv]^T + b  (head epilogue, split at 512)
            gemm_tc_kernel<true><<<ggrid(BL, 2 * Dv, 1), 256>>>(kvsrc, w + (long)Dv * Dv, bb + Dv, Kt, Vt,
                BL, 2 * Dv, Dv, Dv, Dv, 2 * Dv, 0, 0, 0, 1.f, 4);

            // att = scale * Qt @ Kt^T per (b,h)
            gemm_tc_kernel<true><<<ggrid(Lv, Lv, Bv * Hv), 256>>>(Qt, Kt, nullptr, att, att,
                Lv, Lv, DHv, DHv, DHv, Lv,
                (long)Lv * DHv, (long)Lv * DHv, (long)Lv * Lv, scale, 0);

            softmax_kernel<<<Bv * Hv * Lv, 256>>>(att);

            // ctx[b,l,h*64+d] = att @ Vt per (b,h)  (ctx epilogue)
            gemm_tc_kernel<false><<<ggrid(Lv, DHv, Bv * Hv), 256>>>(att, Vt, nullptr, ctx, ctx,
                Lv, DHv, Lv, Lv, DHv, DHv,
                (long)Lv * Lv, (long)Lv * DHv, 0, 1.f, 8);

            // Y = ctx @ Wo^T + bo
            gemm_tc_kernel<true><<<ggrid(BL, Dv, 1), 256>>>(ctx,
                out_w + (long)(i * 2 + j) * Dv * Dv, out_b + (long)(i * 2 + j) * Dv, Y, Y,
                BL, Dv, Dv, Dv, Dv, Dv, 0, 0, 0, 1.f, 0);

            ln_kernel<<<BL, 256>>>(X, Y,
                ln_g + (long)(i * 3 + j) * Dv, ln_b + (long)(i * 3 + j) * Dv);
        }
        gemm_tc_kernel<true><<<ggrid(BL, DFFv, 1), 256>>>(X,
            lin1_w + (long)i * DFFv * Dv, lin1_b + (long)i * DFFv, Hff, Hff,
            BL, DFFv, Dv, Dv, Dv, DFFv, 0, 0, 0, 1.f, 2);
        gemm_tc_kernel<true><<<ggrid(BL, Dv, 1), 256>>>(Hff,
            lin2_w + (long)i * Dv * DFFv, lin2_b + (long)i * Dv, Y, Y,
            BL, Dv, DFFv, DFFv, DFFv, Dv, 0, 0, 0, 1.f, 0);
        ln_kernel<<<BL, 256>>>(X, Y,
            ln_g + (long)(i * 3 + 2) * Dv, ln_b + (long)(i * 3 + 2) * Dv);
    }

    // logits: per batch b, [Tv,VSv] = X[b,C:] @ W_out^T + b_out
    gemm_tc_kernel<true><<<ggrid(Tv, VSv, Bv), 256>>>(X + (long)Cv * Dv, W_out, b_out, out, out,
        Tv, VSv, Dv, Dv, Dv, VSv,
        (long)Lv * Dv, 0, (long)Tv * VSv, 1.f, 0);
}

// round 16
// speedup vs baseline: 1.0059x; 1.0032x over previous
#include <cuda_runtime.h>
#include <cuda_bf16.h>
#include <math.h>
#include <stdint.h>

// Problem constants
#define Bv 8
#define Tv 1024
#define Cv 16
#define Lv 1040      // C + T
#define Dv 512
#define Hv 8
#define DHv 64
#define NLv 2
#define DFFv 2048
#define VSv 8000     // V*S
#define Sv 8

// ---------------- scratch (static device globals; allocation-free) ----------
__device__ float g_X  [Bv * Lv * Dv];
__device__ float g_MEM[Bv * Lv * Dv];
__device__ float g_Qt [Bv * Hv * Lv * DHv];
__device__ float g_Kt [Bv * Hv * Lv * DHv];
__device__ float g_Vt [Bv * Hv * Lv * DHv];
__device__ float g_att[(long)Bv * Hv * Lv * Lv];
__device__ float g_ctx[Bv * Lv * Dv];
__device__ float g_Y  [Bv * Lv * Dv];
__device__ float g_Hff[Bv * Lv * DFFv];

// ---------------- embed ------------------------------------------------------
__global__ __launch_bounds__(256) void embed_kernel(
    const int* __restrict__ token, const int* __restrict__ state,
    const float* __restrict__ prefix, const float* __restrict__ emb,
    const float* __restrict__ b_in, const float* __restrict__ pos,
    float* __restrict__ X, float* __restrict__ MEM)
{
    long i = (long)blockIdx.x * 256 + threadIdx.x;
    if (i >= (long)Bv * Lv * Dv) return;
    int d = (int)(i & (Dv - 1));
    long r = i >> 9;
    int l = (int)(r % Lv);
    int b = (int)(r / Lv);
    float v;
    if (l < Cv) {
        v = prefix[((long)b * Cv + l) * Dv + d];
    } else {
        int t = l - Cv;
        int row = token[b * Tv + t] * Sv + state[b];
        v = emb[(long)row * Dv + d] + b_in[d];
    }
    v += pos[(long)l * Dv + d];
    X[i] = v;
    MEM[i] = v;
}

// ---------------- tf32 tensor-core GEMM, cp.async double-buffered ------------
// C = alpha * A * op(B) + bias ; A:[M,K] lda ; B: TRANSB? [N,K]:[K,N] ldb
// flags: bit1 = relu ; bit2 = QKV head epilogue (C=K/Q head buf, C2=V half)
//        bit3 = ctx epilogue (z=b*H+h, write [b, l, h*64+d])
// Tile: BM=BN=128, BK=16, 256 thr = 8 warps (4Mx2N), warp tile 32x64.

__device__ __forceinline__ void cp16(float* dst, const float* src, int szbytes) {
    uint32_t d = (uint32_t)__cvta_generic_to_shared(dst);
    asm volatile("cp.async.cg.shared.global [%0], [%1], 16, %2;\n"
                 :: "r"(d), "l"(src), "r"(szbytes));
}
__device__ __forceinline__ void cp_commit() {
    asm volatile("cp.async.commit_group;\n");
}
__device__ __forceinline__ uint32_t ldcvt(const float* p) {
    uint32_t r;
    asm("cvt.rna.tf32.f32 %0, %1;" : "=r"(r) : "f"(*p));
    return r;
}
__device__ __forceinline__ void mma_tf32(float* d, const uint32_t* a,
                                         uint32_t b0, uint32_t b1) {
    asm volatile(
        "mma.sync.aligned.m16n8k8.row.col.f32.tf32.tf32.f32 "
        "{%0,%1,%2,%3}, {%4,%5,%6,%7}, {%8,%9}, {%0,%1,%2,%3};\n"
        : "+f"(d[0]), "+f"(d[1]), "+f"(d[2]), "+f"(d[3])
        : "r"(a[0]), "r"(a[1]), "r"(a[2]), "r"(a[3]), "r"(b0), "r"(b1));
}

// A tile: [128 rows][16 k], row stride 20 floats (bank map g*20+t -> distinct)
// B NT  : [128 rows][16 k], row stride 20
// B NN  : [16 k][128 n],    row stride 136 (bank map t*8+g -> distinct)
template<bool TRANSB>
__device__ __forceinline__ void load_tile(
    float* sa, float* sb, const float* A, const float* Bm,
    int m0, int n0, int koff, int M, int N, int lda, int ldb, int tid)
{
#pragma unroll
    for (int it = 0; it < 2; it++) {
        int idx = tid + it * 256;
        int row = idx >> 2, ch = (idx & 3) << 2;
        const float* src = A + (long)(m0 + row) * lda + koff + ch;
        int sz = 16;
        if (m0 + row >= M) { sz = 0; src = A; }
        cp16(sa + row * 20 + ch, src, sz);
    }
    if (TRANSB) {
#pragma unroll
        for (int it = 0; it < 2; it++) {
            int idx = tid + it * 256;
            int row = idx >> 2, ch = (idx & 3) << 2;
            const float* src = Bm + (long)(n0 + row) * ldb + koff + ch;
            int sz = 16;
            if (n0 + row >= N) { sz = 0; src = Bm; }
            cp16(sb + row * 20 + ch, src, sz);
        }
    } else {
#pragma unroll
        for (int it = 0; it < 2; it++) {
            int idx = tid + it * 256;
            int k = idx >> 5, ch = (idx & 31) << 2;
            const float* src = Bm + (long)(koff + k) * ldb + n0 + ch;
            int rem = N - (n0 + ch);
            int sz = rem >= 4 ? 16 : (rem > 0 ? rem * 4 : 0);
            if (sz == 0) src = Bm;
            cp16(sb + k * 136 + ch, src, sz);
        }
    }
    cp_commit();
}

template<bool TRANSB>
__global__ __launch_bounds__(256) void gemm_tc_kernel(
    const float* __restrict__ A, const float* __restrict__ Bm,
    const float* __restrict__ bias, float* __restrict__ C, float* __restrict__ C2,
    int M, int N, int K, int lda, int ldb, int ldc,
    long strA, long strB, long strC, float alpha, int flags)
{
    __shared__ __align__(16) float sA[2][128 * 20];
    __shared__ __align__(16) float sB[2][2560];   // NT: 128*20 ; NN: 16*136

    int z = blockIdx.z;
    A  += (long)z * strA;
    Bm += (long)z * strB;
    C  += (long)z * strC;
    int m0 = blockIdx.y * 128, n0 = blockIdx.x * 128;
    int tid = threadIdx.x;
    int warp = tid >> 5, lane = tid & 31;
    int wm = warp >> 1, wn = warp & 1;
    int g = lane >> 2, t = lane & 3;

    float acc[2][8][4];
#pragma unroll
    for (int mt = 0; mt < 2; mt++)
#pragma unroll
        for (int nt = 0; nt < 8; nt++)
#pragma unroll
            for (int q = 0; q < 4; q++) acc[mt][nt][q] = 0.f;

    const int nk = K >> 4;   // all K multiples of 16

    load_tile<TRANSB>(sA[0], sB[0], A, Bm, m0, n0, 0, M, N, lda, ldb, tid);

    for (int kt = 0; kt < nk; kt++) {
        int cur = kt & 1;
        if (kt + 1 < nk) {
            load_tile<TRANSB>(sA[1 - cur], sB[1 - cur], A, Bm, m0, n0,
                              (kt + 1) << 4, M, N, lda, ldb, tid);
            asm volatile("cp.async.wait_group 1;\n");
        } else {
            asm volatile("cp.async.wait_group 0;\n");
        }
        __syncthreads();

        const float* sa = sA[cur];
        const float* sb = sB[cur];
#pragma unroll
        for (int ks = 0; ks < 2; ks++) {
            int k0 = ks * 8;
            uint32_t aF[2][4];
#pragma unroll
            for (int mt = 0; mt < 2; mt++) {
                int rb = wm * 32 + mt * 16;
                aF[mt][0] = ldcvt(&sa[(rb + g) * 20 + k0 + t]);
                aF[mt][1] = ldcvt(&sa[(rb + g + 8) * 20 + k0 + t]);
                aF[mt][2] = ldcvt(&sa[(rb + g) * 20 + k0 + t + 4]);
                aF[mt][3] = ldcvt(&sa[(rb + g + 8) * 20 + k0 + t + 4]);
            }
#pragma unroll
            for (int nt = 0; nt < 8; nt++) {
                int cb = wn * 64 + nt * 8;
                uint32_t b0, b1;
                if (TRANSB) {
                    b0 = ldcvt(&sb[(cb + g) * 20 + k0 + t]);
                    b1 = ldcvt(&sb[(cb + g) * 20 + k0 + t + 4]);
                } else {
                    b0 = ldcvt(&sb[(k0 + t) * 136 + cb + g]);
                    b1 = ldcvt(&sb[(k0 + t + 4) * 136 + cb + g]);
                }
                mma_tf32(acc[0][nt], aF[0], b0, b1);
                mma_tf32(acc[1][nt], aF[1], b0, b1);
            }
        }
        __syncthreads();
    }

    // ---------------- epilogue ----------------
    const bool relu = (flags & 2);
#pragma unroll
    for (int mt = 0; mt < 2; mt++) {
        int rowA = m0 + wm * 32 + mt * 16 + g;
#pragma unroll
        for (int half = 0; half < 2; half++) {
            int row = rowA + half * 8;
            if (row >= M) continue;
#pragma unroll
            for (int nt = 0; nt < 8; nt++) {
                int col = n0 + wn * 64 + nt * 8 + t * 2;
                if (col >= N) continue;   // N even, col even
                float v0 = acc[mt][nt][half * 2 + 0] * alpha;
                float v1 = acc[mt][nt][half * 2 + 1] * alpha;
                if (bias) { v0 += bias[col]; v1 += bias[col + 1]; }
                if (relu) { v0 = fmaxf(v0, 0.f); v1 = fmaxf(v1, 0.f); }
                float* dst;
                if (flags & 4) {          // QKV head epilogue
                    float* base = C; int c = col;
                    if (c >= Dv) { base = C2; c -= Dv; }
                    int b = row / Lv, l = row - b * Lv;
                    dst = base + (((long)(b * Hv + (c >> 6)) * Lv + l) << 6) + (c & 63);
                } else if (flags & 8) {   // ctx epilogue: z=b*H+h, row=l, col=d
                    int b = z >> 3, h = z & 7;
                    dst = C + ((long)(b * Lv + row) * Dv) + (h << 6) + col;
                } else {
                    dst = C + (long)row * ldc + col;
                }
                *(float2*)dst = make_float2(v0, v1);
            }
        }
    }
}

// ---------------- softmax ------------------------------------------------------
__global__ __launch_bounds__(256) void softmax_kernel(float* __restrict__ att)
{
    long row = blockIdx.x;
    float* p = att + row * (long)Lv;
    int tid = threadIdx.x;
    float vals[5];
    int cnt = 0;
    float mx = -1e30f;
    for (int c = tid; c < Lv; c += 256) { vals[cnt] = p[c]; mx = fmaxf(mx, vals[cnt]); cnt++; }
    __shared__ float red[256];
    red[tid] = mx; __syncthreads();
#pragma unroll
    for (int s = 128; s > 0; s >>= 1) { if (tid < s) red[tid] = fmaxf(red[tid], red[tid + s]); __syncthreads(); }
    mx = red[0]; __syncthreads();
    float sum = 0.f;
    for (int i = 0; i < cnt; i++) { vals[i] = expf(vals[i] - mx); sum += vals[i]; }
    red[tid] = sum; __syncthreads();
#pragma unroll
    for (int s = 128; s > 0; s >>= 1) { if (tid < s) red[tid] += red[tid + s]; __syncthreads(); }
    float inv = 1.f / red[0];
    cnt = 0;
    for (int c = tid; c < Lv; c += 256) { p[c] = vals[cnt] * inv; cnt++; }
}

// ---------------- residual + LayerNorm ----------------------------------------
__global__ __launch_bounds__(256) void ln_kernel(
    float* __restrict__ X, const float* __restrict__ Y,
    const float* __restrict__ g, const float* __restrict__ b)
{
    long row = blockIdx.x;
    float* x = X + row * (long)Dv;
    const float* y = Y + row * (long)Dv;
    int tid = threadIdx.x;
    float v0 = x[tid] + y[tid];
    float v1 = x[tid + 256] + y[tid + 256];
    __shared__ float red[256];
    red[tid] = v0 + v1; __syncthreads();
#pragma unroll
    for (int s = 128; s > 0; s >>= 1) { if (tid < s) red[tid] += red[tid + s]; __syncthreads(); }
    float mu = red[0] * (1.f / Dv); __syncthreads();
    float d0 = v0 - mu, d1 = v1 - mu;
    red[tid] = d0 * d0 + d1 * d1; __syncthreads();
#pragma unroll
    for (int s = 128; s > 0; s >>= 1) { if (tid < s) red[tid] += red[tid + s]; __syncthreads(); }
    float rstd = rsqrtf(red[0] * (1.f / Dv) + 1e-5f);
    x[tid]       = d0 * rstd * g[tid]       + b[tid];
    x[tid + 256] = d1 * rstd * g[tid + 256] + b[tid + 256];
}

// ---------------- host orchestration -----------------------------------------
static inline dim3 ggrid(int M, int N, int batch) {
    return dim3((N + 127) / 128, (M + 127) / 128, batch);
}

#define GEMM_NT(Aa,Bb,bi,Cc,C2,M,N,K,lda,ldb,ldc,sA,sB,sC,al,fl) \
    gemm_tc_kernel<true><<<ggrid(M,N, (sA||sB||sC)?((sC== (long)Lv*Lv)?Bv*Hv:Bv):1 ), 256>>>(0,0,0,0,0,0,0,0,0,0,0,0,0,0,0.f,0)
// (macro unused; explicit launches below)

extern "C" void kernel_launch(void* const* d_in, const int* in_sizes, int n_in,
                              void* d_out, int out_size)
{
    const int*   token  = (const int*)  d_in[0];
    const int*   state  = (const int*)  d_in[1];
    const float* prefix = (const float*)d_in[2];
    const float* emb    = (const float*)d_in[3];
    const float* b_in   = (const float*)d_in[4];
    const float* pos    = (const float*)d_in[5];
    const float* W_out  = (const float*)d_in[6];
    const float* b_out  = (const float*)d_in[7];
    const float* qkv_w  = (const float*)d_in[8];
    const float* qkv_b  = (const float*)d_in[9];
    const float* out_w  = (const float*)d_in[10];
    const float* out_b  = (const float*)d_in[11];
    const float* lin1_w = (const float*)d_in[12];
    const float* lin1_b = (const float*)d_in[13];
    const float* lin2_w = (const float*)d_in[14];
    const float* lin2_b = (const float*)d_in[15];
    const float* ln_g   = (const float*)d_in[16];
    const float* ln_b   = (const float*)d_in[17];
    float* out = (float*)d_out;

    float *X, *MEM, *Qt, *Kt, *Vt, *att, *ctx, *Y, *Hff;
    cudaGetSymbolAddress((void**)&X,   g_X);
    cudaGetSymbolAddress((void**)&MEM, g_MEM);
    cudaGetSymbolAddress((void**)&Qt,  g_Qt);
    cudaGetSymbolAddress((void**)&Kt,  g_Kt);
    cudaGetSymbolAddress((void**)&Vt,  g_Vt);
    cudaGetSymbolAddress((void**)&att, g_att);
    cudaGetSymbolAddress((void**)&ctx, g_ctx);
    cudaGetSymbolAddress((void**)&Y,   g_Y);
    cudaGetSymbolAddress((void**)&Hff, g_Hff);

    const int BL = Bv * Lv;
    const long nEmb = (long)Bv * Lv * Dv;

    embed_kernel<<<(int)((nEmb + 255) / 256), 256>>>(token, state, prefix, emb, b_in, pos, X, MEM);

    const float scale = 1.f / 8.f;

    for (int i = 0; i < NLv; i++) {
        for (int j = 0; j < 2; j++) {
            const float* kvsrc = (j == 0) ? X : MEM;
            const float* w  = qkv_w + (long)(i * 2 + j) * 3 * Dv * Dv;
            const float* bb = qkv_b + (long)(i * 2 + j) * 3 * Dv;

            // Qt[b,h,l,d] = X @ Wq^T + bq  (head epilogue)
            gemm_tc_kernel<true><<<ggrid(BL, Dv, 1), 256>>>(X, w, bb, Qt, Qt,
                BL, Dv, Dv, Dv, Dv, Dv, 0, 0, 0, 1.f, 4);
            // Kt|Vt = kvsrc @ [Wk;Wv]^T + b  (head epilogue, split at 512)
            gemm_tc_kernel<true><<<ggrid(BL, 2 * Dv, 1), 256>>>(kvsrc, w + (long)Dv * Dv, bb + Dv, Kt, Vt,
                BL, 2 * Dv, Dv, Dv, Dv, 2 * Dv, 0, 0, 0, 1.f, 4);

            // att = scale * Qt @ Kt^T per (b,h)
            gemm_tc_kernel<true><<<ggrid(Lv, Lv, Bv * Hv), 256>>>(Qt, Kt, nullptr, att, att,
                Lv, Lv, DHv, DHv, DHv, Lv,
                (long)Lv * DHv, (long)Lv * DHv, (long)Lv * Lv, scale, 0);

            softmax_kernel<<<Bv * Hv * Lv, 256>>>(att);

            // ctx[b,l,h*64+d] = att @ Vt per (b,h)  (ctx epilogue)
            gemm_tc_kernel<false><<<ggrid(Lv, DHv, Bv * Hv), 256>>>(att, Vt, nullptr, ctx, ctx,
                Lv, DHv, Lv, Lv, DHv, DHv,
                (long)Lv * Lv, (long)Lv * DHv, 0, 1.f, 8);

            // Y = ctx @ Wo^T + bo
            gemm_tc_kernel<true><<<ggrid(BL, Dv, 1), 256>>>(ctx,
                out_w + (long)(i * 2 + j) * Dv * Dv, out_b + (long)(i * 2 + j) * Dv, Y, Y,
                BL, Dv, Dv, Dv, Dv, Dv, 0, 0, 0, 1.f, 0);

            ln_kernel<<<BL, 256>>>(X, Y,
                ln_g + (long)(i * 3 + j) * Dv, ln_b + (long)(i * 3 + j) * Dv);
        }
        gemm_tc_kernel<true><<<ggrid(BL, DFFv, 1), 256>>>(X,
            lin1_w + (long)i * DFFv * Dv, lin1_b + (long)i * DFFv, Hff, Hff,
            BL, DFFv, Dv, Dv, Dv, DFFv, 0, 0, 0, 1.f, 2);
        gemm_tc_kernel<true><<<ggrid(BL, Dv, 1), 256>>>(Hff,
            lin2_w + (long)i * Dv * DFFv, lin2_b + (long)i * Dv, Y, Y,
            BL, Dv, DFFv, DFFv, DFFv, Dv, 0, 0, 0, 1.f, 0);
        ln_kernel<<<BL, 256>>>(X, Y,
            ln_g + (long)(i * 3 + 2) * Dv, ln_b + (long)(i * 3 + 2) * Dv);
    }

    // logits: per batch b, [Tv,VSv] = X[b,C:] @ W_out^T + b_out
    gemm_tc_kernel<true><<<ggrid(Tv, VSv, Bv), 256>>>(X + (long)Cv * Dv, W_out, b_out, out, out,
        Tv, VSv, Dv, Dv, Dv, VSv,
        (long)Lv * Dv, 0, (long)Tv * VSv, 1.f, 0);
}